// round 7
// baseline (speedup 1.0000x reference)
#include <cuda_runtime.h>
#include <cuda_bf16.h>

// ---------------------------------------------------------------------------
// QuantumLayerVQC — 3-qubit, 3-layer VQC, B ~ 1M samples.
//
// z(b) = psi(b)^T ReM psi(b), psi = kron_q (cos x_q/2, sin x_q/2),
// ReM = Re(U^dag Z0 U) depends only on q_weights. Per qubit the quadratic
// monomials {c^2, s^2, cs} map to {1, cos x, sin x} (double angle), so z is
// trilinear in m_q = (1, cos x_q, sin x_q) with 27 coefficients D.
//
// Kernel 1 (1 block): evolve 8 basis columns -> U -> ReM -> D[27].
// Kernel 2: per block, ONE 32KB cp.async.bulk (GMEM->SMEM, async proxy, no
//   register pressure), D loads overlapped with the copy, then 4 samples per
//   thread from SMEM. DRAM-bound by construction: wave 1 puts ~23MB in flight.
// ---------------------------------------------------------------------------

__device__ float g_D[27];

__device__ __forceinline__ void swp(float& a, float& b) { float t = a; a = b; b = t; }

__global__ void vqc_setup_kernel(const float* __restrict__ w) {
    // w: (3 layers, 3 qubits, 2) = 18 floats: [l][q][0]=RY angle, [l][q][1]=RZ angle
    __shared__ float Ur[8][8];  // [amplitude k][column j]
    __shared__ float Ui[8][8];
    __shared__ float Ms[8][8];  // ReM

    int t = threadIdx.x;

    if (t < 8) {
        // Evolve basis column j = t through the parameterized circuit.
        float ur[8], ui[8];
        #pragma unroll
        for (int k = 0; k < 8; k++) { ur[k] = (k == t) ? 1.f : 0.f; ui[k] = 0.f; }

        for (int l = 0; l < 3; l++) {
            for (int q = 0; q < 3; q++) {
                float thy = w[(l * 3 + q) * 2 + 0];
                float thz = w[(l * 3 + q) * 2 + 1];
                int s = 4 >> q;  // bit stride: q0->4, q1->2, q2->1

                // RY(thy): real rotation on (i, i+s) pairs. __sincosf abs err
                // ~1e-7, far under the 1e-3 rel-err budget.
                float cy, sy; __sincosf(0.5f * thy, &sy, &cy);
                #pragma unroll
                for (int i = 0; i < 8; i++) {
                    if (i & s) continue;
                    float ar = ur[i],     ai = ui[i];
                    float br = ur[i + s], bi = ui[i + s];
                    ur[i]     = cy * ar - sy * br;  ui[i]     = cy * ai - sy * bi;
                    ur[i + s] = sy * ar + cy * br;  ui[i + s] = sy * ai + cy * bi;
                }

                // RZ(thz): bit=0 -> e^{-i thz/2}, bit=1 -> e^{+i thz/2}
                float cz, sz; __sincosf(0.5f * thz, &sz, &cz);
                #pragma unroll
                for (int i = 0; i < 8; i++) {
                    float ph = (i & s) ? sz : -sz;  // imaginary part of phase
                    float ar = ur[i], ai = ui[i];
                    ur[i] = cz * ar - ph * ai;
                    ui[i] = cz * ai + ph * ar;
                }
            }
            // CNOT01 (control bit2, target bit1): swap 4<->6, 5<->7
            swp(ur[4], ur[6]); swp(ui[4], ui[6]);
            swp(ur[5], ur[7]); swp(ui[5], ui[7]);
            // CNOT12 (control bit1, target bit0): swap 2<->3, 6<->7
            swp(ur[2], ur[3]); swp(ui[2], ui[3]);
            swp(ur[6], ur[7]); swp(ui[6], ui[7]);
        }
        #pragma unroll
        for (int k = 0; k < 8; k++) { Ur[k][t] = ur[k]; Ui[k][t] = ui[k]; }
    }
    __syncthreads();

    if (t < 64) {
        // ReM[i][j] = sum_k sign(k) * Re(conj(U[k][i]) * U[k][j]),
        // sign = +1 for k<4 (q0=0), -1 otherwise.
        int i = t >> 3, j = t & 7;
        float m = 0.f;
        #pragma unroll
        for (int k = 0; k < 8; k++) {
            float sgn = (k < 4) ? 1.f : -1.f;
            m += sgn * (Ur[k][i] * Ur[k][j] + Ui[k][i] * Ui[k][j]);
        }
        Ms[i][j] = m;
    }
    __syncthreads();

    if (t < 27) {
        // Per-qubit pair-(b,b') -> (1, cos, sin) basis transform:
        //   c^2 = 1/2 + 1/2 cos,  c*s = 1/2 sin,  s^2 = 1/2 - 1/2 cos
        const float T[4][3] = {
            {0.5f,  0.5f, 0.0f},   // (0,0)
            {0.0f,  0.0f, 0.5f},   // (0,1)
            {0.0f,  0.0f, 0.5f},   // (1,0)
            {0.5f, -0.5f, 0.0f},   // (1,1)
        };
        int p0 = t / 9, p1 = (t / 3) % 3, p2 = t % 3;
        float d = 0.f;
        #pragma unroll
        for (int i = 0; i < 8; i++) {
            #pragma unroll
            for (int j = 0; j < 8; j++) {
                int pr0 = (((i >> 2) & 1) << 1) | ((j >> 2) & 1);
                int pr1 = (((i >> 1) & 1) << 1) | ((j >> 1) & 1);
                int pr2 = ((i & 1) << 1) | (j & 1);
                d += Ms[i][j] * T[pr0][p0] * T[pr1][p1] * T[pr2][p2];
            }
        }
        g_D[t] = d;
    }
}

static constexpr int TPB = 256;
static constexpr int ROWS_PER_BLOCK = 1024;                 // 32 KB per block
static constexpr int STAGE_BYTES = ROWS_PER_BLOCK * 32;

__device__ __forceinline__ float vqc_eval(const float* __restrict__ D,
                                          float x0, float x1, float x2) {
    float s0, c0, s1, c1, s2, c2;
    __sincosf(x0, &s0, &c0);
    __sincosf(x1, &s1, &c1);
    __sincosf(x2, &s2, &c2);

    float z = 0.f;
    #pragma unroll
    for (int p0 = 0; p0 < 3; p0++) {
        float u = 0.f;
        #pragma unroll
        for (int p1 = 0; p1 < 3; p1++) {
            const float* d = &D[p0 * 9 + p1 * 3];
            float v = fmaf(d[2], s2, fmaf(d[1], c2, d[0]));
            float m1 = (p1 == 0) ? 1.f : ((p1 == 1) ? c1 : s1);
            u = fmaf(v, m1, u);
        }
        float m0 = (p0 == 0) ? 1.f : ((p0 == 1) ? c0 : s0);
        z = fmaf(u, m0, z);
    }
    return z;
}

__global__ void __launch_bounds__(TPB) vqc_main_kernel(
    const float* __restrict__ in,  // (B, 8) floats, rows 32B
    float* __restrict__ out,       // (B,)
    int B
) {
    __shared__ __align__(128) char buf[STAGE_BYTES];
    __shared__ __align__(8) unsigned long long mbar;

    int base = blockIdx.x * ROWS_PER_BLOCK;
    int rows = B - base;
    if (rows > ROWS_PER_BLOCK) rows = ROWS_PER_BLOCK;
    if (rows <= 0) return;

    unsigned mbar_a = (unsigned)__cvta_generic_to_shared(&mbar);
    unsigned buf_a  = (unsigned)__cvta_generic_to_shared(buf);

    if (threadIdx.x == 0) {
        asm volatile("mbarrier.init.shared.b64 [%0], %1;"
                     :: "r"(mbar_a), "r"(1u) : "memory");
    }
    __syncthreads();

    if (threadIdx.x == 0) {
        unsigned bytes = (unsigned)rows * 32u;  // multiple of 16 always
        asm volatile("mbarrier.arrive.expect_tx.shared.b64 _, [%0], %1;"
                     :: "r"(mbar_a), "r"(bytes) : "memory");
        asm volatile(
            "cp.async.bulk.shared::cta.global.mbarrier::complete_tx::bytes "
            "[%0], [%1], %2, [%3];"
            :: "r"(buf_a), "l"(in + (size_t)base * 8), "r"(bytes), "r"(mbar_a)
            : "memory");
    }

    // Overlap the warp-uniform coefficient loads with the bulk copy.
    float D[27];
    #pragma unroll
    for (int i = 0; i < 27; i++) D[i] = g_D[i];

    // Wait for the bulk copy (acquire orders subsequent generic smem loads).
    {
        unsigned done;
        asm volatile(
            "{\n\t.reg .pred p;\n\t"
            "mbarrier.try_wait.parity.acquire.cta.shared::cta.b64 p, [%1], 0;\n\t"
            "selp.b32 %0, 1, 0, p;\n\t}"
            : "=r"(done) : "r"(mbar_a) : "memory");
        if (!done) {
            asm volatile(
                "{\n\t.reg .pred P1;\n\t"
                "WAIT_LOOP_%=:\n\t"
                "mbarrier.try_wait.parity.acquire.cta.shared::cta.b64 P1, [%0], 0, 0x989680;\n\t"
                "@P1 bra.uni WAIT_DONE_%=;\n\t"
                "bra.uni WAIT_LOOP_%=;\n\t"
                "WAIT_DONE_%=:\n\t}"
                :: "r"(mbar_a) : "memory");
        }
    }

    const float4* rowbuf = reinterpret_cast<const float4*>(buf);
    #pragma unroll
    for (int k = 0; k < ROWS_PER_BLOCK / TPB; k++) {
        int r = threadIdx.x + k * TPB;
        if (r < rows) {
            float4 x = rowbuf[2 * r];  // first 16B of the 32B row
            out[base + r] = vqc_eval(D, x.x, x.y, x.z);
        }
    }
}

extern "C" void kernel_launch(void* const* d_in, const int* in_sizes, int n_in,
                              void* d_out, int out_size) {
    // inputs: (B,8) float32; q_weights: (3,3,2)=18 float32.  Be robust to order.
    const float* in = (const float*)d_in[0];
    const float* w  = (const float*)d_in[1];
    int sz0 = in_sizes[0], sz1 = in_sizes[1];
    if (sz0 == 18 && sz1 != 18) {
        const float* tmp = in; in = w; w = tmp;
        int ts = sz0; sz0 = sz1; sz1 = ts;
    }
    int B = sz0 / 8;
    float* out = (float*)d_out;

    vqc_setup_kernel<<<1, 64>>>(w);
    int grid = (B + ROWS_PER_BLOCK - 1) / ROWS_PER_BLOCK;
    vqc_main_kernel<<<grid, TPB>>>(in, out, B);
}

// round 12
// speedup vs baseline: 1.0845x; 1.0845x over previous
#include <cuda_runtime.h>
#include <cuda_bf16.h>

// ---------------------------------------------------------------------------
// QuantumLayerVQC — 3-qubit, 3-layer VQC, B ~ 1M samples.
//
// z(b) = psi(b)^T ReM psi(b), psi = kron_q (cos x_q/2, sin x_q/2),
// ReM = Re(U^dag Z0 U) depends only on q_weights. Per qubit the quadratic
// monomials {c^2, s^2, cs} map to {1, cos x, sin x} (double angle), so z is
// trilinear in m_q = (1, cos x_q, sin x_q) with 27 coefficients D.
//
// SINGLE persistent kernel:
//  - each block redundantly computes D[27] (tiny), overlapped with its
//    prologue bulk copies (removes the setup launch + dependency gap);
//  - 4-deep cp.async.bulk ring of 8KB tiles, grid-strided: while computing
//    tile k, copies for k+1..k+3 are in flight and the consumed stage is
//    re-armed immediately -> continuous DRAM demand (vs 40% duty one-shot).
// ---------------------------------------------------------------------------

static constexpr int TPB    = 256;
static constexpr int TILE   = 256;   // rows per stage = 8 KB
static constexpr int STAGES = 4;     // 32 KB ring
static constexpr int MAXGRID = 456;  // ~3 blocks/SM on 148-152 SMs

__device__ __forceinline__ void swp(float& a, float& b) { float t = a; a = b; b = t; }

__device__ __forceinline__ void mbar_wait(unsigned mbar_a, unsigned phase) {
    unsigned done;
    asm volatile(
        "{\n\t.reg .pred p;\n\t"
        "mbarrier.try_wait.parity.acquire.cta.shared::cta.b64 p, [%1], %2;\n\t"
        "selp.b32 %0, 1, 0, p;\n\t}"
        : "=r"(done) : "r"(mbar_a), "r"(phase) : "memory");
    if (!done) {
        asm volatile(
            "{\n\t.reg .pred P1;\n\t"
            "WAIT_LOOP_%=:\n\t"
            "mbarrier.try_wait.parity.acquire.cta.shared::cta.b64 P1, [%0], %1, 0x989680;\n\t"
            "@P1 bra.uni WAIT_DONE_%=;\n\t"
            "bra.uni WAIT_LOOP_%=;\n\t"
            "WAIT_DONE_%=:\n\t}"
            :: "r"(mbar_a), "r"(phase) : "memory");
    }
}

__device__ __forceinline__ float vqc_eval(const float* __restrict__ D,
                                          float x0, float x1, float x2) {
    float s0, c0, s1, c1, s2, c2;
    __sincosf(x0, &s0, &c0);
    __sincosf(x1, &s1, &c1);
    __sincosf(x2, &s2, &c2);

    float z = 0.f;
    #pragma unroll
    for (int p0 = 0; p0 < 3; p0++) {
        float u = 0.f;
        #pragma unroll
        for (int p1 = 0; p1 < 3; p1++) {
            const float* d = &D[p0 * 9 + p1 * 3];
            float v = fmaf(d[2], s2, fmaf(d[1], c2, d[0]));
            float m1 = (p1 == 0) ? 1.f : ((p1 == 1) ? c1 : s1);
            u = fmaf(v, m1, u);
        }
        float m0 = (p0 == 0) ? 1.f : ((p0 == 1) ? c0 : s0);
        z = fmaf(u, m0, z);
    }
    return z;
}

__global__ void __launch_bounds__(TPB, 3) vqc_kernel(
    const float* __restrict__ in,  // (B, 8) floats, rows 32B
    const float* __restrict__ w,   // (3,3,2) = 18 floats
    float* __restrict__ out,       // (B,)
    int B
) {
    __shared__ __align__(128) float4 buf[STAGES][TILE * 2];  // 4 x 8 KB
    __shared__ __align__(8) unsigned long long mbar[STAGES];
    __shared__ float Ur[8][8], Ui[8][8], Ms[8][8], Dsh[27];

    const int t = threadIdx.x;
    const int ntiles = (B + TILE - 1) / TILE;
    const int grid = gridDim.x;

    unsigned mbar_a[STAGES];
    #pragma unroll
    for (int s = 0; s < STAGES; s++)
        mbar_a[s] = (unsigned)__cvta_generic_to_shared(&mbar[s]);

    if (t < STAGES) {
        asm volatile("mbarrier.init.shared.b64 [%0], %1;"
                     :: "r"(mbar_a[t]), "r"(1u) : "memory");
    }
    __syncthreads();

    // ---- prologue: fire the first STAGES copies; DRAM starts immediately ----
    if (t == 0) {
        #pragma unroll
        for (int p = 0; p < STAGES; p++) {
            int tile = blockIdx.x + p * grid;
            if (tile < ntiles) {
                int base = tile * TILE;
                int rows = min(TILE, B - base);
                unsigned bytes = (unsigned)rows * 32u;
                unsigned dst = (unsigned)__cvta_generic_to_shared(&buf[p][0]);
                asm volatile("mbarrier.arrive.expect_tx.shared.b64 _, [%0], %1;"
                             :: "r"(mbar_a[p]), "r"(bytes) : "memory");
                asm volatile(
                    "cp.async.bulk.shared::cta.global.mbarrier::complete_tx::bytes "
                    "[%0], [%1], %2, [%3];"
                    :: "r"(dst), "l"(in + (size_t)base * 8), "r"(bytes), "r"(mbar_a[p])
                    : "memory");
            }
        }
    }

    // ---- fused setup (overlapped with the in-flight copies) ----
    if (t < 8) {
        // Evolve basis column j = t through the parameterized circuit.
        float ur[8], ui[8];
        #pragma unroll
        for (int k = 0; k < 8; k++) { ur[k] = (k == t) ? 1.f : 0.f; ui[k] = 0.f; }

        for (int l = 0; l < 3; l++) {
            for (int q = 0; q < 3; q++) {
                float thy = w[(l * 3 + q) * 2 + 0];
                float thz = w[(l * 3 + q) * 2 + 1];
                int s = 4 >> q;  // bit stride: q0->4, q1->2, q2->1

                // RY: real rotation on (i, i+s) pairs. __sincosf abs err ~1e-7.
                float cy, sy; __sincosf(0.5f * thy, &sy, &cy);
                #pragma unroll
                for (int i = 0; i < 8; i++) {
                    if (i & s) continue;
                    float ar = ur[i],     ai = ui[i];
                    float br = ur[i + s], bi = ui[i + s];
                    ur[i]     = cy * ar - sy * br;  ui[i]     = cy * ai - sy * bi;
                    ur[i + s] = sy * ar + cy * br;  ui[i + s] = sy * ai + cy * bi;
                }
                // RZ: bit=0 -> e^{-i thz/2}, bit=1 -> e^{+i thz/2}
                float cz, sz; __sincosf(0.5f * thz, &sz, &cz);
                #pragma unroll
                for (int i = 0; i < 8; i++) {
                    float ph = (i & s) ? sz : -sz;
                    float ar = ur[i], ai = ui[i];
                    ur[i] = cz * ar - ph * ai;
                    ui[i] = cz * ai + ph * ar;
                }
            }
            // CNOT01: swap 4<->6, 5<->7 ; CNOT12: swap 2<->3, 6<->7
            swp(ur[4], ur[6]); swp(ui[4], ui[6]);
            swp(ur[5], ur[7]); swp(ui[5], ui[7]);
            swp(ur[2], ur[3]); swp(ui[2], ui[3]);
            swp(ur[6], ur[7]); swp(ui[6], ui[7]);
        }
        #pragma unroll
        for (int k = 0; k < 8; k++) { Ur[k][t] = ur[k]; Ui[k][t] = ui[k]; }
    }
    __syncthreads();

    if (t < 64) {
        // ReM[i][j] = sum_k sign(k) Re(conj(U[k][i]) U[k][j]); sign=+1 for k<4.
        int i = t >> 3, j = t & 7;
        float m = 0.f;
        #pragma unroll
        for (int k = 0; k < 8; k++) {
            float sgn = (k < 4) ? 1.f : -1.f;
            m += sgn * (Ur[k][i] * Ur[k][j] + Ui[k][i] * Ui[k][j]);
        }
        Ms[i][j] = m;
    }
    __syncthreads();

    if (t < 27) {
        // Pair-(b,b') -> (1, cos, sin): c^2 = .5+.5cos, cs = .5sin, s^2 = .5-.5cos
        const float T[4][3] = {
            {0.5f,  0.5f, 0.0f}, {0.0f, 0.0f, 0.5f},
            {0.0f,  0.0f, 0.5f}, {0.5f, -0.5f, 0.0f},
        };
        int p0 = t / 9, p1 = (t / 3) % 3, p2 = t % 3;
        float d = 0.f;
        #pragma unroll
        for (int i = 0; i < 8; i++) {
            #pragma unroll
            for (int j = 0; j < 8; j++) {
                int pr0 = (((i >> 2) & 1) << 1) | ((j >> 2) & 1);
                int pr1 = (((i >> 1) & 1) << 1) | ((j >> 1) & 1);
                int pr2 = ((i & 1) << 1) | (j & 1);
                d += Ms[i][j] * T[pr0][p0] * T[pr1][p1] * T[pr2][p2];
            }
        }
        Dsh[t] = d;
    }
    __syncthreads();

    float D[27];
    #pragma unroll
    for (int i = 0; i < 27; i++) D[i] = Dsh[i];

    // ---- persistent pipelined mainloop ----
    int k = 0;
    for (int tile = blockIdx.x; tile < ntiles; tile += grid, k++) {
        int s = k & (STAGES - 1);
        unsigned phase = (unsigned)((k >> 2) & 1);

        mbar_wait(mbar_a[s], phase);

        int base = tile * TILE;
        int rows = min(TILE, B - base);
        if (t < rows) {
            float4 x = buf[s][2 * t];  // first 16B of the 32B row
            out[base + t] = vqc_eval(D, x.x, x.y, x.z);
        }
        __syncthreads();  // all reads of stage s done

        int nx = tile + STAGES * grid;
        if (t == 0 && nx < ntiles) {
            // generic reads -> async write (WAR): cross-proxy fence
            asm volatile("fence.proxy.async.shared::cta;" ::: "memory");
            int nbase = nx * TILE;
            int nrows = min(TILE, B - nbase);
            unsigned bytes = (unsigned)nrows * 32u;
            unsigned dst = (unsigned)__cvta_generic_to_shared(&buf[s][0]);
            asm volatile("mbarrier.arrive.expect_tx.shared.b64 _, [%0], %1;"
                         :: "r"(mbar_a[s]), "r"(bytes) : "memory");
            asm volatile(
                "cp.async.bulk.shared::cta.global.mbarrier::complete_tx::bytes "
                "[%0], [%1], %2, [%3];"
                :: "r"(dst), "l"(in + (size_t)nbase * 8), "r"(bytes), "r"(mbar_a[s])
                : "memory");
        }
    }
}

extern "C" void kernel_launch(void* const* d_in, const int* in_sizes, int n_in,
                              void* d_out, int out_size) {
    // inputs: (B,8) float32; q_weights: (3,3,2)=18 float32.  Be robust to order.
    const float* in = (const float*)d_in[0];
    const float* w  = (const float*)d_in[1];
    int sz0 = in_sizes[0], sz1 = in_sizes[1];
    if (sz0 == 18 && sz1 != 18) {
        const float* tmp = in; in = w; w = tmp;
        int ts = sz0; sz0 = sz1; sz1 = ts;
    }
    int B = sz0 / 8;
    float* out = (float*)d_out;

    int ntiles = (B + TILE - 1) / TILE;
    int grid = ntiles < MAXGRID ? ntiles : MAXGRID;
    vqc_kernel<<<grid, TPB>>>(in, w, out, B);
}